// round 15
// baseline (speedup 1.0000x reference)
#include <cuda_runtime.h>
#include <cuda_fp16.h>
#include <cstdint>

#define NN 50000
#define NE 800000
#define DD 128
#define MP 50048              // 391 * 128 padded rows
#define BN_EPS 1e-5f

#define SCAN_B 256
#define SCAN_G ((NN + SCAN_B - 1) / SCAN_B)   // 196

// ---------------- scratch (device globals) ----------------
__device__ float g_h2[NN * DD];               // layer-1 pre-BN output (fp32)
__device__ uint16_t g_h2h[(size_t)NN * DD];   // layer-0 pre-BN output (fp16)
__device__ uint16_t g_a1[(size_t)MP * 256];   // MLP A fp16: [hi(128)|lo(128)]
__device__ uint16_t g_b1[2 * 256 * 256];      // W1 fp16 per layer: [n, hi|hi]
__device__ uint16_t g_b2[2 * 128 * 512];      // W2 fp16 per layer: [n, k(256 used)]
__device__ uint8_t  g_ctab[NN];               // combined embedding index (0..8)
__device__ float    g_htab[9 * 128];          // 9 distinct node embeddings (fp32)
__device__ unsigned long long g_pk1[NN];      // cnt1: 7 fields x 9 bits
__device__ unsigned long long g_pk2[NN];      // cnt2: 3x6 bits | cnt3: 9x5 bits @18
__device__ int   g_rowptr[NN + 1];
__device__ int   g_wr[NN];
__device__ int   g_col[NE];
__device__ float g_colsum[2 * DD];
__device__ float g_colsq[2 * DD];
__device__ int   g_bsum[SCAN_G];
__device__ int   g_boff[SCAN_G];
__device__ unsigned int g_tick;
__device__ unsigned int g_flag;

// ---------------- helpers ----------------
__device__ __forceinline__ uint32_t s2u(const void* p) {
    uint32_t a;
    asm("{ .reg .u64 t; cvta.to.shared.u64 t, %1; cvt.u32.u64 %0, t; }" : "=r"(a) : "l"(p));
    return a;
}
#define SWZ(x) ((x) ^ (((x) >> 3) & 0x70))

#define CP_A16(dst, src) \
    asm volatile("cp.async.cg.shared.global [%0], [%1], 16;" :: "r"(dst), "l"(src))
#define CP_COMMIT() asm volatile("cp.async.commit_group;")
#define CP_WAIT(n)  asm volatile("cp.async.wait_group %0;" :: "n"(n))

#define LDSM_X4(r0, r1, r2, r3, addr) \
    asm volatile("ldmatrix.sync.aligned.m8n8.x4.shared.b16 {%0,%1,%2,%3}, [%4];" \
        : "=r"(r0), "=r"(r1), "=r"(r2), "=r"(r3) : "r"(addr))
#define MMA16816(d, a, b) \
    asm volatile("mma.sync.aligned.m16n8k16.row.col.f32.f16.f16.f32 " \
        "{%0,%1,%2,%3}, {%4,%5,%6,%7}, {%8,%9}, {%0,%1,%2,%3};" \
        : "+f"((d)[0]), "+f"((d)[1]), "+f"((d)[2]), "+f"((d)[3]) \
        : "r"((a)[0]), "r"((a)[1]), "r"((a)[2]), "r"((a)[3]), \
          "r"((b)[0]), "r"((b)[1]))

__device__ __forceinline__ void split_f16(float v, uint16_t& hi, uint16_t& lo) {
    __half h = __float2half_rn(v);
    float rem = v - __half2float(h);
    __half l = __float2half_rn(rem);
    hi = __half_as_ushort(h);
    lo = __half_as_ushort(l);
}

// ---------------- setupA: prerequisites of hist/agg0 ----------------
#define UA0 (2 * NN)                      // pk1 + pk2 zero
#define UA1 (UA0 + 512)                   // BN stats
#define UA2 (UA1 + NN)                    // ctab
#define UA3 (UA2 + 9 * 128)               // htab
#define UA4 (UA3 + 2)                     // tick + flag
__global__ void setupA_kernel(const int* __restrict__ x,
                              const float* __restrict__ xemb1,
                              const float* __restrict__ xemb2) {
    int i = blockIdx.x * blockDim.x + threadIdx.x;
    if (i >= UA4) return;
    if (i < UA0) {
        if (i < NN) g_pk1[i] = 0ull;
        else g_pk2[i - NN] = 0ull;
    } else if (i < UA1) {
        int j = i - UA0;
        if (j < 256) g_colsum[j] = 0.f;
        else g_colsq[j - 256] = 0.f;
    } else if (i < UA2) {
        int v = i - UA1;
        int c = x[2 * v] * 3 + x[2 * v + 1];
        g_ctab[v] = (uint8_t)min(c, 8);
    } else if (i < UA3) {
        int j = i - UA2;
        int c = j >> 7, d = j & 127;
        g_htab[j] = xemb1[(c / 3) * DD + d] + xemb2[(c % 3) * DD + d];
    } else if (i == UA3) {
        g_tick = 0u;
    } else {
        g_flag = 0u;
    }
}

// ---------------- setupB: fp16 weight builds ----------------
#define UB0 (2 * 128 * 256)               // b1 builds
#define UB1 (UB0 + 2 * 256 * 128)         // b2 builds
__global__ void setupB_kernel(const float* __restrict__ W1,
                              const float* __restrict__ W2) {
    int i = blockIdx.x * blockDim.x + threadIdx.x;
    if (i >= UB1) return;
    if (i < UB0) {
        int l = i >> 15;
        int r = i & 32767;          // k*256+n
        int k = r >> 8, n = r & 255;
        uint16_t hv = __half_as_ushort(__float2half_rn(W1[(size_t)l * 32768 + r]));
        g_b1[(size_t)l * 65536 + n * 256 + k]       = hv;
        g_b1[(size_t)l * 65536 + n * 256 + 128 + k] = hv;
    } else {
        int j = i - UB0;
        int l = j >> 15;
        int r = j & 32767;          // k*128+n
        int k = r >> 7, n = r & 127;
        uint16_t hv = __half_as_ushort(__float2half_rn(W2[(size_t)l * 32768 + r]));
        g_b2[(size_t)l * 65536 + n * 512 + k] = hv;
    }
}

// ---------------- histogram: 2 packed u64 atomics per edge ----------------
__global__ void hist_kernel(const int* __restrict__ edge_index,
                            const int* __restrict__ edge_attr) {
    int e = blockIdx.x * blockDim.x + threadIdx.x;
    if (e >= NE) return;
    int src = edge_index[e];
    int dst = edge_index[NE + e];
    int2 at = ((const int2*)edge_attr)[e];
    int c = g_ctab[src];
    atomicAdd(&g_pk1[dst], 1ull << (9 * at.x));
    atomicAdd(&g_pk2[dst], (1ull << (6 * at.y)) + (1ull << (18 + 5 * c)));
}

__device__ __forceinline__ int node_deg(int i) {
    unsigned long long p = g_pk1[i];
    int d = 0;
#pragma unroll
    for (int t = 0; t < 7; t++) d += (int)((p >> (9 * t)) & 511ull);
    return d;
}

// ---------------- single-kernel CSR scan (ticket + flag release) ----------
__global__ void scanF_kernel() {
    __shared__ int sh[SCAN_B];
    __shared__ bool lastBlk;
    int t = threadIdx.x;
    int i = blockIdx.x * SCAN_B + t;
    int d = (i < NN) ? node_deg(i) : 0;
    sh[t] = d;
    __syncthreads();
    for (int off = SCAN_B / 2; off > 0; off >>= 1) {
        if (t < off) sh[t] += sh[t + off];
        __syncthreads();
    }
    if (t == 0) {
        g_bsum[blockIdx.x] = sh[0];
        __threadfence();
        unsigned tk = atomicAdd(&g_tick, 1u);
        lastBlk = (tk == gridDim.x - 1);
    }
    __syncthreads();
    if (lastBlk) {
        __threadfence();
        int v = (t < SCAN_G) ? g_bsum[t] : 0;
        sh[t] = v;
        __syncthreads();
        for (int off = 1; off < SCAN_B; off <<= 1) {
            int u = (t >= off) ? sh[t - off] : 0;
            __syncthreads();
            sh[t] += u;
            __syncthreads();
        }
        if (t < SCAN_G) g_boff[t] = (t == 0) ? 0 : sh[t - 1];
        __threadfence();
        __syncthreads();
        if (t == 0) atomicExch(&g_flag, 1u);
    }
    if (t == 0) {
        while (atomicAdd(&g_flag, 0u) == 0u) {}
    }
    __syncthreads();
    __threadfence();
    sh[t] = d;
    __syncthreads();
    for (int off = 1; off < SCAN_B; off <<= 1) {
        int v = (t >= off) ? sh[t - off] : 0;
        __syncthreads();
        sh[t] += v;
        __syncthreads();
    }
    if (i < NN) {
        int excl = g_boff[blockIdx.x] + sh[t] - d;
        g_rowptr[i] = excl;
        g_wr[i] = excl;
        if (i == NN - 1) g_rowptr[NN] = excl + d;
    }
}

__global__ void scatter_kernel(const int* __restrict__ edge_index) {
    int e = blockIdx.x * blockDim.x + threadIdx.x;
    if (e >= NE) return;
    int src = edge_index[e];
    int dst = edge_index[NE + e];
    int pos = atomicAdd(&g_wr[dst], 1);
    g_col[pos] = src;
}

// ---------------- layer-0 aggregation: pure count-based ----------
__global__ __launch_bounds__(256) void aggregate0_kernel(
        const float* __restrict__ e1l, const float* __restrict__ e2l) {
    __shared__ float4 ht[9 * 32];
    __shared__ float4 se[(7 + 3) * 32];
    int tid = threadIdx.x;
    for (int i = tid; i < 9 * 32; i += 256) ht[i] = ((const float4*)g_htab)[i];
    for (int i = tid; i < 320; i += 256)
        se[i] = (i < 224) ? ((const float4*)e1l)[i] : ((const float4*)e2l)[i - 224];
    __syncthreads();

    int warp = tid >> 5;
    int lane = tid & 31;
    int v = blockIdx.x * 8 + warp;
    if (v >= NN) return;

    unsigned long long p1 = g_pk1[v];
    unsigned long long p2 = g_pk2[v];

    float4 acc = ht[g_ctab[v] * 32 + lane];
    float4 t4 = se[4 * 32 + lane];
    acc.x += t4.x; acc.y += t4.y; acc.z += t4.z; acc.w += t4.w;
    t4 = se[7 * 32 + lane];
    acc.x += t4.x; acc.y += t4.y; acc.z += t4.z; acc.w += t4.w;

#pragma unroll
    for (int t = 0; t < 7; t++) {
        int c = (int)((p1 >> (9 * t)) & 511ull);
        if (c) {
            float fc = (float)c;
            float4 ev = se[t * 32 + lane];
            acc.x += fc * ev.x; acc.y += fc * ev.y; acc.z += fc * ev.z; acc.w += fc * ev.w;
        }
    }
#pragma unroll
    for (int t = 0; t < 3; t++) {
        int c = (int)((p2 >> (6 * t)) & 63ull);
        if (c) {
            float fc = (float)c;
            float4 ev = se[(7 + t) * 32 + lane];
            acc.x += fc * ev.x; acc.y += fc * ev.y; acc.z += fc * ev.z; acc.w += fc * ev.w;
        }
    }
#pragma unroll
    for (int c = 0; c < 9; c++) {
        int k = (int)((p2 >> (18 + 5 * c)) & 31ull);
        if (k) {
            float fk = (float)k;
            float4 ev = ht[c * 32 + lane];
            acc.x += fk * ev.x; acc.y += fk * ev.y; acc.z += fk * ev.z; acc.w += fk * ev.w;
        }
    }
    uint16_t h0, h1, h2, h3, l0, l1, l2, l3;
    split_f16(acc.x, h0, l0);
    split_f16(acc.y, h1, l1);
    split_f16(acc.z, h2, l2);
    split_f16(acc.w, h3, l3);
    uint2 hv2, lv2;
    hv2.x = (uint32_t)h0 | ((uint32_t)h1 << 16);
    hv2.y = (uint32_t)h2 | ((uint32_t)h3 << 16);
    lv2.x = (uint32_t)l0 | ((uint32_t)l1 << 16);
    lv2.y = (uint32_t)l2 | ((uint32_t)l3 << 16);
    *(uint2*)(g_a1 + (size_t)v * 256 + lane * 4) = hv2;
    *(uint2*)(g_a1 + (size_t)v * 256 + 128 + lane * 4) = lv2;
}

// ---------------- layer-1 aggregation: fp16 gathers + fused BN+relu --------
__global__ __launch_bounds__(256) void aggregate1_kernel(
        const uint16_t* __restrict__ Hh,
        const float* __restrict__ e1l, const float* __restrict__ e2l,
        const float* __restrict__ gamma, const float* __restrict__ beta,
        const float* __restrict__ ssum, const float* __restrict__ ssq) {
    __shared__ float4 se[(7 + 3) * 32];
    for (int i = threadIdx.x; i < 320; i += 256)
        se[i] = (i < 224) ? ((const float4*)e1l)[i] : ((const float4*)e2l)[i - 224];
    __syncthreads();

    int tid = threadIdx.x;
    int warp = tid >> 5;
    int lane = tid & 31;
    int v = blockIdx.x * 8 + warp;
    if (v >= NN) return;

    int cc = lane * 4;
    float invn = 1.0f / (float)NN;
    float scl[4], sft[4];
#pragma unroll
    for (int k = 0; k < 4; k++) {
        float mu = ssum[cc + k] * invn;
        float var = ssq[cc + k] * invn - mu * mu;
        float rs = rsqrtf(var + BN_EPS);
        scl[k] = gamma[cc + k] * rs;
        sft[k] = beta[cc + k] - mu * scl[k];
    }

    auto cvt = [&](uint2 raw) -> float4 {
        float2 f0 = __half22float2(*reinterpret_cast<const __half2*>(&raw.x));
        float2 f1 = __half22float2(*reinterpret_cast<const __half2*>(&raw.y));
        float4 x;
        x.x = fmaxf(fmaf(f0.x, scl[0], sft[0]), 0.f);
        x.y = fmaxf(fmaf(f0.y, scl[1], sft[1]), 0.f);
        x.z = fmaxf(fmaf(f1.x, scl[2], sft[2]), 0.f);
        x.w = fmaxf(fmaf(f1.y, scl[3], sft[3]), 0.f);
        return x;
    };

    float4 acc = cvt(*(const uint2*)(Hh + (size_t)v * DD + lane * 4));
    float4 t4 = se[4 * 32 + lane];
    acc.x += t4.x; acc.y += t4.y; acc.z += t4.z; acc.w += t4.w;
    t4 = se[7 * 32 + lane];
    acc.x += t4.x; acc.y += t4.y; acc.z += t4.z; acc.w += t4.w;

    float4 acc2 = make_float4(0.f, 0.f, 0.f, 0.f);
    int beg = g_rowptr[v];
    int end = g_rowptr[v + 1];
    int j = beg;
    for (; j + 7 < end; j += 8) {
        uint2 raw[8];
#pragma unroll
        for (int q = 0; q < 8; q++)
            raw[q] = *(const uint2*)(Hh + (size_t)g_col[j + q] * DD + lane * 4);
#pragma unroll
        for (int q = 0; q < 8; q += 2) {
            float4 a0 = cvt(raw[q]);
            float4 a1 = cvt(raw[q + 1]);
            if (q & 2) {
                acc2.x += a0.x + a1.x; acc2.y += a0.y + a1.y;
                acc2.z += a0.z + a1.z; acc2.w += a0.w + a1.w;
            } else {
                acc.x += a0.x + a1.x; acc.y += a0.y + a1.y;
                acc.z += a0.z + a1.z; acc.w += a0.w + a1.w;
            }
        }
    }
    for (; j < end; j++) {
        float4 hv = cvt(*(const uint2*)(Hh + (size_t)g_col[j] * DD + lane * 4));
        acc.x += hv.x; acc.y += hv.y; acc.z += hv.z; acc.w += hv.w;
    }
    acc.x += acc2.x; acc.y += acc2.y; acc.z += acc2.z; acc.w += acc2.w;

    unsigned long long p1 = g_pk1[v];
    unsigned long long p2 = g_pk2[v];
#pragma unroll
    for (int t = 0; t < 7; t++) {
        int c = (int)((p1 >> (9 * t)) & 511ull);
        if (c) {
            float fc = (float)c;
            float4 ev = se[t * 32 + lane];
            acc.x += fc * ev.x; acc.y += fc * ev.y; acc.z += fc * ev.z; acc.w += fc * ev.w;
        }
    }
#pragma unroll
    for (int t = 0; t < 3; t++) {
        int c = (int)((p2 >> (6 * t)) & 63ull);
        if (c) {
            float fc = (float)c;
            float4 ev = se[(7 + t) * 32 + lane];
            acc.x += fc * ev.x; acc.y += fc * ev.y; acc.z += fc * ev.z; acc.w += fc * ev.w;
        }
    }
    uint16_t h0, h1, h2, h3, l0, l1, l2, l3;
    split_f16(acc.x, h0, l0);
    split_f16(acc.y, h1, l1);
    split_f16(acc.z, h2, l2);
    split_f16(acc.w, h3, l3);
    uint2 hv2, lv2;
    hv2.x = (uint32_t)h0 | ((uint32_t)h1 << 16);
    hv2.y = (uint32_t)h2 | ((uint32_t)h3 << 16);
    lv2.x = (uint32_t)l0 | ((uint32_t)l1 << 16);
    lv2.y = (uint32_t)l2 | ((uint32_t)l3 << 16);
    *(uint2*)(g_a1 + (size_t)v * 256 + lane * 4) = hv2;
    *(uint2*)(g_a1 + (size_t)v * 256 + 128 + lane * 4) = lv2;
}

// ---------------- fused MLP (512 threads, 16 warps as 4x4) ----------------
// mid = relu(A x W1 + b1); out = mid x W2 + b2.
// A [MP,256] fp16 (hi|lo). B1 [256n,256k] (hi|hi dup). B2 [128n,512k] (256 used).
// mid: 8 SW128 tiles of [128,64] fp16 in smem (hi 0..3, lo 4..7).
template <bool OUT16>
__global__ void __launch_bounds__(512, 1)
mlp_fused_kernel(const uint16_t* __restrict__ A,
                 const uint16_t* __restrict__ B1m,
                 const uint16_t* __restrict__ B2m,
                 const float* __restrict__ bias1,
                 const float* __restrict__ bias2,
                 float* __restrict__ outF,
                 uint16_t* __restrict__ outF16,
                 float* __restrict__ statSum,
                 float* __restrict__ statSq) {
    extern __shared__ char smem[];
    float* sB1 = (float*)smem;                   // 256 f
    float* sB2 = (float*)(smem + 1024);          // 128 f
    char* scrA = smem + 2048;                    // 2 x 16KB (ph1 A / ph2 B2)
    char* scrB = smem + 2048 + 32768;            // 32KB (ph1 B1, single buf)
    char* mid  = smem + 67584;                   // 8 x 16KB
    const int tid = threadIdx.x;
    const int wid = tid >> 5;
    const int lane = tid & 31;
    const int m0 = blockIdx.x * 128;
    const int wm = (wid >> 2) * 32;              // 4 row groups of 32
    const int wn2 = (wid & 3) * 64;              // phase 1 (N=256)
    const int wn3 = (wid & 3) * 32;              // phase 2 (N=128)

    if (tid < 256) sB1[tid] = bias1[tid];
    else if (tid < 384) sB2[tid - 256] = bias2[tid - 256];

    // ================= phase 1 =================
    float acc1[2][8][4];
#pragma unroll
    for (int i = 0; i < 2; i++)
#pragma unroll
        for (int j = 0; j < 8; j++)
#pragma unroll
            for (int k = 0; k < 4; k++) acc1[i][j][k] = 0.f;

    auto loadA1 = [&](int c, int buf) {
        const uint16_t* Ag = A + (size_t)m0 * 256 + c * 64;
        uint32_t ab = s2u(scrA + buf * 16384);
#pragma unroll
        for (int i = 0; i < 2; i++) {
            int idx = tid + i * 512;
            int r = idx >> 3, u = idx & 7;
            CP_A16(ab + SWZ(r * 128 + u * 16), Ag + (size_t)r * 256 + u * 8);
        }
    };
    auto loadB1c = [&](int c) {
        const uint16_t* Bg = B1m + c * 64;
        uint32_t bb = s2u(scrB);
#pragma unroll
        for (int i = 0; i < 4; i++) {
            int idx = tid + i * 512;
            int r = idx >> 3, u = idx & 7;
            CP_A16(bb + SWZ(r * 128 + u * 16), Bg + (size_t)r * 256 + u * 8);
        }
    };

    loadA1(0, 0); CP_COMMIT();
    for (int c = 0; c < 4; c++) {
        int buf = c & 1;
        loadB1c(c); CP_COMMIT();
        if (c < 3) { loadA1(c + 1, buf ^ 1); CP_COMMIT(); CP_WAIT(1); }
        else CP_WAIT(0);
        __syncthreads();
        uint32_t aBase = s2u(scrA + buf * 16384);
        uint32_t bBase = s2u(scrB);
#pragma unroll
        for (int ks = 0; ks < 4; ks++) {
            int k0b = ks * 32;
            uint32_t af[2][4];
#pragma unroll
            for (int mt = 0; mt < 2; mt++) {
                int row = wm + mt * 16 + (lane & 15);
                LDSM_X4(af[mt][0], af[mt][1], af[mt][2], af[mt][3],
                        aBase + SWZ(row * 128 + k0b + ((lane >> 4) << 4)));
            }
            uint32_t bfr[8][2];
#pragma unroll
            for (int p = 0; p < 4; p++) {
                int g = lane >> 3;
                int nrow = wn2 + p * 16 + (lane & 7) + ((g >> 1) << 3);
                uint32_t r0, r1, r2, r3;
                LDSM_X4(r0, r1, r2, r3, bBase + SWZ(nrow * 128 + k0b + ((g & 1) << 4)));
                bfr[2 * p][0] = r0; bfr[2 * p][1] = r1;
                bfr[2 * p + 1][0] = r2; bfr[2 * p + 1][1] = r3;
            }
#pragma unroll
            for (int mt = 0; mt < 2; mt++)
#pragma unroll
                for (int nt = 0; nt < 8; nt++)
                    MMA16816(acc1[mt][nt], af[mt], bfr[nt]);
        }
        __syncthreads();
    }

    // phase-1 epilogue: bias + relu + fp16 split -> mid tiles
#pragma unroll
    for (int nt = 0; nt < 8; nt++) {
        int cl = wn2 + nt * 8 + 2 * (lane & 3);   // 0..255
        float b0 = sB1[cl], b1v = sB1[cl + 1];
        int th = cl >> 6;                          // hi tile 0..3
        int ln2 = (cl & 63) * 2;                   // byte offset in 128B row
#pragma unroll
        for (int mt = 0; mt < 2; mt++) {
#pragma unroll
            for (int h = 0; h < 2; h++) {
                int m = wm + mt * 16 + (lane >> 2) + h * 8;   // local row
                float v0 = fmaxf(acc1[mt][nt][2 * h] + b0, 0.f);
                float v1 = fmaxf(acc1[mt][nt][2 * h + 1] + b1v, 0.f);
                uint16_t h0, l0, h1, l1;
                split_f16(v0, h0, l0);
                split_f16(v1, h1, l1);
                *(uint32_t*)(mid + th * 16384 + SWZ(m * 128 + ln2)) =
                    (uint32_t)h0 | ((uint32_t)h1 << 16);
                *(uint32_t*)(mid + (4 + th) * 16384 + SWZ(m * 128 + ln2)) =
                    (uint32_t)l0 | ((uint32_t)l1 << 16);
            }
        }
    }
    __syncthreads();

    // ================= phase 2 =================
    float acc2[2][4][4];
#pragma unroll
    for (int i = 0; i < 2; i++)
#pragma unroll
        for (int j = 0; j < 4; j++)
#pragma unroll
            for (int k = 0; k < 4; k++) acc2[i][j][k] = 0.f;

    auto loadB2c = [&](int c, int buf) {
        const uint16_t* Bg = B2m + c * 64;
        uint32_t bb = s2u(scrA + buf * 16384);
#pragma unroll
        for (int i = 0; i < 2; i++) {
            int idx = tid + i * 512;
            int r = idx >> 3, u = idx & 7;
            CP_A16(bb + SWZ(r * 128 + u * 16), Bg + (size_t)r * 512 + u * 8);
        }
    };

    loadB2c(0, 0); CP_COMMIT();
    for (int c = 0; c < 4; c++) {
        int buf = c & 1;
        if (c < 3) { loadB2c(c + 1, buf ^ 1); CP_COMMIT(); CP_WAIT(1); }
        else CP_WAIT(0);
        __syncthreads();
        uint32_t bBase = s2u(scrA + buf * 16384);
#pragma unroll
        for (int part = 0; part < 2; part++) {
            uint32_t aBase = s2u(mid + (part * 4 + c) * 16384);
#pragma unroll
            for (int ks = 0; ks < 4; ks++) {
                int k0b = ks * 32;
                uint32_t af[2][4];
#pragma unroll
                for (int mt = 0; mt < 2; mt++) {
                    int row = wm + mt * 16 + (lane & 15);
                    LDSM_X4(af[mt][0], af[mt][1], af[mt][2], af[mt][3],
                            aBase + SWZ(row * 128 + k0b + ((lane >> 4) << 4)));
                }
                uint32_t bfr[4][2];
#pragma unroll
                for (int p = 0; p < 2; p++) {
                    int g = lane >> 3;
                    int nrow = wn3 + p * 16 + (lane & 7) + ((g >> 1) << 3);
                    uint32_t r0, r1, r2, r3;
                    LDSM_X4(r0, r1, r2, r3,
                            bBase + SWZ(nrow * 128 + k0b + ((g & 1) << 4)));
                    bfr[2 * p][0] = r0; bfr[2 * p][1] = r1;
                    bfr[2 * p + 1][0] = r2; bfr[2 * p + 1][1] = r3;
                }
#pragma unroll
                for (int mt = 0; mt < 2; mt++)
#pragma unroll
                    for (int nt = 0; nt < 4; nt++)
                        MMA16816(acc2[mt][nt], af[mt], bfr[nt]);
            }
        }
        __syncthreads();
    }

    // phase-2 epilogue: bias + store + fused BN stats
#pragma unroll
    for (int nt = 0; nt < 4; nt++) {
        int cl = wn3 + nt * 8 + 2 * (lane & 3);
        float b0 = sB2[cl], b1v = sB2[cl + 1];
        float s0 = 0.f, s1 = 0.f, q0 = 0.f, q1 = 0.f;
#pragma unroll
        for (int mt = 0; mt < 2; mt++) {
#pragma unroll
            for (int h = 0; h < 2; h++) {
                int m = m0 + wm + mt * 16 + (lane >> 2) + h * 8;
                float v0 = acc2[mt][nt][2 * h] + b0;
                float v1 = acc2[mt][nt][2 * h + 1] + b1v;
                if (m < NN) {
                    if (OUT16) {
                        __half2 hp = __floats2half2_rn(v0, v1);
                        *(uint32_t*)(outF16 + (size_t)m * 128 + cl) =
                            *reinterpret_cast<uint32_t*>(&hp);
                    } else {
                        float2 v; v.x = v0; v.y = v1;
                        *(float2*)(outF + (size_t)m * 128 + cl) = v;
                    }
                    s0 += v0; s1 += v1;
                    q0 += v0 * v0; q1 += v1 * v1;
                }
            }
        }
#pragma unroll
        for (int off = 16; off >= 4; off >>= 1) {
            s0 += __shfl_down_sync(0xffffffff, s0, off);
            s1 += __shfl_down_sync(0xffffffff, s1, off);
            q0 += __shfl_down_sync(0xffffffff, q0, off);
            q1 += __shfl_down_sync(0xffffffff, q1, off);
        }
        if (lane < 4) {
            atomicAdd(&statSum[cl], s0);
            atomicAdd(&statSum[cl + 1], s1);
            atomicAdd(&statSq[cl], q0);
            atomicAdd(&statSq[cl + 1], q1);
        }
    }
}

// ---------------- final BN apply ----------------
__global__ void bn_apply_kernel(const float* __restrict__ X,
                                const float* __restrict__ gamma,
                                const float* __restrict__ beta,
                                const float* __restrict__ ssum,
                                const float* __restrict__ ssq,
                                float* __restrict__ Y) {
    int idx = blockIdx.x * blockDim.x + threadIdx.x;
    if (idx >= NN * (DD / 4)) return;
    int v = idx >> 5;
    int c4 = idx & 31;
    int c = c4 * 4;
    float4 x = ((const float4*)(X + (size_t)v * DD))[c4];
    float invn = 1.0f / (float)NN;
    float o[4];
    float xi[4] = {x.x, x.y, x.z, x.w};
#pragma unroll
    for (int k = 0; k < 4; k++) {
        float mu = ssum[c + k] * invn;
        float var = ssq[c + k] * invn - mu * mu;
        float rs = rsqrtf(var + BN_EPS);
        o[k] = gamma[c + k] * (xi[k] - mu) * rs + beta[c + k];
    }
    ((float4*)(Y + (size_t)v * DD))[c4] = make_float4(o[0], o[1], o[2], o[3]);
}

// ---------------- launch ----------------
extern "C" void kernel_launch(void* const* d_in, const int* in_sizes, int n_in,
                              void* d_out, int out_size) {
    const int* x          = (const int*)d_in[0];
    const int* edge_index = (const int*)d_in[1];
    const int* edge_attr  = (const int*)d_in[2];
    const float* xemb1 = (const float*)d_in[4];
    const float* xemb2 = (const float*)d_in[5];
    const float* e1    = (const float*)d_in[6];
    const float* e2    = (const float*)d_in[7];
    const float* W1    = (const float*)d_in[8];
    const float* b1    = (const float*)d_in[9];
    const float* W2    = (const float*)d_in[10];
    const float* b2    = (const float*)d_in[11];
    const float* gamma = (const float*)d_in[12];
    const float* beta  = (const float*)d_in[13];
    float* out = (float*)d_out;

    float *p_h2, *p_sum, *p_sq;
    uint16_t *p_h2h, *p_a1, *p_b1, *p_b2;
    cudaGetSymbolAddress((void**)&p_h2,  g_h2);
    cudaGetSymbolAddress((void**)&p_h2h, g_h2h);
    cudaGetSymbolAddress((void**)&p_a1,  g_a1);
    cudaGetSymbolAddress((void**)&p_b1,  g_b1);
    cudaGetSymbolAddress((void**)&p_b2,  g_b2);
    cudaGetSymbolAddress((void**)&p_sum, g_colsum);
    cudaGetSymbolAddress((void**)&p_sq,  g_colsq);

    constexpr int SMEM_F = 67584 + 8 * 16384;   // 198656 B
    cudaFuncSetAttribute(mlp_fused_kernel<true>,
                         cudaFuncAttributeMaxDynamicSharedMemorySize, SMEM_F);
    cudaFuncSetAttribute(mlp_fused_kernel<false>,
                         cudaFuncAttributeMaxDynamicSharedMemorySize, SMEM_F);

    static cudaStream_t sCSR = nullptr, sWB = nullptr;
    static cudaEvent_t evInit = nullptr, evHist = nullptr, evWB = nullptr, evCSR = nullptr;
    if (!sCSR) {
        cudaStreamCreateWithFlags(&sCSR, cudaStreamNonBlocking);
        cudaStreamCreateWithFlags(&sWB, cudaStreamNonBlocking);
        cudaEventCreateWithFlags(&evInit, cudaEventDisableTiming);
        cudaEventCreateWithFlags(&evHist, cudaEventDisableTiming);
        cudaEventCreateWithFlags(&evWB, cudaEventDisableTiming);
        cudaEventCreateWithFlags(&evCSR, cudaEventDisableTiming);
    }

    // weight builds overlap everything up to first GEMM
    cudaEventRecord(evInit, 0);
    cudaStreamWaitEvent(sWB, evInit, 0);
    setupB_kernel<<<(UB1 + 255) / 256, 256, 0, sWB>>>(W1, W2);
    cudaEventRecord(evWB, sWB);

    setupA_kernel<<<(UA4 + 255) / 256, 256>>>(x, xemb1, xemb2);
    hist_kernel<<<(NE + 255) / 256, 256>>>(edge_index, edge_attr);
    cudaEventRecord(evHist, 0);

    // CSR chain on side stream (needed only by layer-1 aggregation)
    cudaStreamWaitEvent(sCSR, evHist, 0);
    scanF_kernel<<<SCAN_G, SCAN_B, 0, sCSR>>>();
    scatter_kernel<<<(NE + 255) / 256, 256, 0, sCSR>>>(edge_index);
    cudaEventRecord(evCSR, sCSR);

    // layer 0
    aggregate0_kernel<<<(NN + 7) / 8, 256>>>(e1, e2);
    cudaStreamWaitEvent(0, evWB, 0);
    mlp_fused_kernel<true><<<MP / 128, 512, SMEM_F>>>(
        p_a1, p_b1, p_b2, b1, b2, nullptr, p_h2h, p_sum, p_sq);

    // layer 1
    cudaStreamWaitEvent(0, evCSR, 0);
    aggregate1_kernel<<<(NN + 7) / 8, 256>>>(
        p_h2h, e1 + 7 * DD, e2 + 3 * DD, gamma, beta, p_sum, p_sq);
    mlp_fused_kernel<false><<<MP / 128, 512, SMEM_F>>>(
        p_a1, p_b1 + 65536, p_b2 + 65536, b1 + 2 * DD, b2 + DD,
        p_h2, nullptr, p_sum + DD, p_sq + DD);

    bn_apply_kernel<<<(NN * 32 + 255) / 256, 256>>>(
        p_h2, gamma + DD, beta + DD, p_sum + DD, p_sq + DD, out);
}

// round 16
// speedup vs baseline: 1.0429x; 1.0429x over previous
#include <cuda_runtime.h>
#include <cuda_fp16.h>
#include <cstdint>

#define NN 50000
#define NE 800000
#define DD 128
#define MP 50048              // 391 * 128 padded rows
#define BN_EPS 1e-5f

#define SCAN_B 256
#define SCAN_G ((NN + SCAN_B - 1) / SCAN_B)   // 196

// ---------------- scratch (device globals) ----------------
__device__ float g_h2[NN * DD];               // layer-1 pre-BN output (fp32)
__device__ uint16_t g_h2h[(size_t)NN * DD];   // layer-0 pre-BN output (fp16)
__device__ uint16_t g_a1[(size_t)MP * 256];   // MLP A fp16: [hi(128)|lo(128)]
__device__ uint16_t g_b1[2 * 256 * 256];      // W1 fp16 per layer: [n, hi|hi]
__device__ uint16_t g_b2[2 * 128 * 512];      // W2 fp16 per layer: [n, k(256 used)]
__device__ uint8_t  g_ctab[NN];               // combined embedding index (0..8)
__device__ float    g_htab[9 * 128];          // 9 distinct node embeddings (fp32)
__device__ unsigned long long g_pk1[NN];      // cnt1: 7 fields x 9 bits
__device__ unsigned long long g_pk2[NN];      // cnt2: 3x6 bits | cnt3: 9x5 bits @18
__device__ int   g_rowptr[NN + 1];
__device__ int   g_wr[NN];
__device__ int   g_col[NE];
__device__ float g_colsum[2 * DD];
__device__ float g_colsq[2 * DD];
__device__ int   g_bsum[SCAN_G];
__device__ int   g_boff[SCAN_G];
__device__ unsigned int g_tick;
__device__ unsigned int g_flag;

// ---------------- helpers ----------------
__device__ __forceinline__ uint32_t s2u(const void* p) {
    uint32_t a;
    asm("{ .reg .u64 t; cvta.to.shared.u64 t, %1; cvt.u32.u64 %0, t; }" : "=r"(a) : "l"(p));
    return a;
}
#define SWZ(x) ((x) ^ (((x) >> 3) & 0x70))

#define CP_A16(dst, src) \
    asm volatile("cp.async.cg.shared.global [%0], [%1], 16;" :: "r"(dst), "l"(src))
#define CP_COMMIT() asm volatile("cp.async.commit_group;")
#define CP_WAIT(n)  asm volatile("cp.async.wait_group %0;" :: "n"(n))

#define LDSM_X4(r0, r1, r2, r3, addr) \
    asm volatile("ldmatrix.sync.aligned.m8n8.x4.shared.b16 {%0,%1,%2,%3}, [%4];" \
        : "=r"(r0), "=r"(r1), "=r"(r2), "=r"(r3) : "r"(addr))
#define MMA16816(d, a, b) \
    asm volatile("mma.sync.aligned.m16n8k16.row.col.f32.f16.f16.f32 " \
        "{%0,%1,%2,%3}, {%4,%5,%6,%7}, {%8,%9}, {%0,%1,%2,%3};" \
        : "+f"((d)[0]), "+f"((d)[1]), "+f"((d)[2]), "+f"((d)[3]) \
        : "r"((a)[0]), "r"((a)[1]), "r"((a)[2]), "r"((a)[3]), \
          "r"((b)[0]), "r"((b)[1]))

__device__ __forceinline__ void split_f16(float v, uint16_t& hi, uint16_t& lo) {
    __half h = __float2half_rn(v);
    float rem = v - __half2float(h);
    __half l = __float2half_rn(rem);
    hi = __half_as_ushort(h);
    lo = __half_as_ushort(l);
}

// ---------------- setupA: prerequisites of hist/agg0 ----------------
#define UA0 (2 * NN)                      // pk1 + pk2 zero
#define UA1 (UA0 + 512)                   // BN stats
#define UA2 (UA1 + NN)                    // ctab
#define UA3 (UA2 + 9 * 128)               // htab
#define UA4 (UA3 + 2)                     // tick + flag
__global__ void setupA_kernel(const int* __restrict__ x,
                              const float* __restrict__ xemb1,
                              const float* __restrict__ xemb2) {
    int i = blockIdx.x * blockDim.x + threadIdx.x;
    if (i >= UA4) return;
    if (i < UA0) {
        if (i < NN) g_pk1[i] = 0ull;
        else g_pk2[i - NN] = 0ull;
    } else if (i < UA1) {
        int j = i - UA0;
        if (j < 256) g_colsum[j] = 0.f;
        else g_colsq[j - 256] = 0.f;
    } else if (i < UA2) {
        int v = i - UA1;
        int c = x[2 * v] * 3 + x[2 * v + 1];
        g_ctab[v] = (uint8_t)min(c, 8);
    } else if (i < UA3) {
        int j = i - UA2;
        int c = j >> 7, d = j & 127;
        g_htab[j] = xemb1[(c / 3) * DD + d] + xemb2[(c % 3) * DD + d];
    } else if (i == UA3) {
        g_tick = 0u;
    } else {
        g_flag = 0u;
    }
}

// ---------------- setupB: fp16 weight builds ----------------
#define UB0 (2 * 128 * 256)               // b1 builds
#define UB1 (UB0 + 2 * 256 * 128)         // b2 builds
__global__ void setupB_kernel(const float* __restrict__ W1,
                              const float* __restrict__ W2) {
    int i = blockIdx.x * blockDim.x + threadIdx.x;
    if (i >= UB1) return;
    if (i < UB0) {
        int l = i >> 15;
        int r = i & 32767;          // k*256+n
        int k = r >> 8, n = r & 255;
        uint16_t hv = __half_as_ushort(__float2half_rn(W1[(size_t)l * 32768 + r]));
        g_b1[(size_t)l * 65536 + n * 256 + k]       = hv;
        g_b1[(size_t)l * 65536 + n * 256 + 128 + k] = hv;
    } else {
        int j = i - UB0;
        int l = j >> 15;
        int r = j & 32767;          // k*128+n
        int k = r >> 7, n = r & 127;
        uint16_t hv = __half_as_ushort(__float2half_rn(W2[(size_t)l * 32768 + r]));
        g_b2[(size_t)l * 65536 + n * 512 + k] = hv;
    }
}

// ---------------- histogram: 2 packed u64 atomics per edge ----------------
__global__ void hist_kernel(const int* __restrict__ edge_index,
                            const int* __restrict__ edge_attr) {
    int e = blockIdx.x * blockDim.x + threadIdx.x;
    if (e >= NE) return;
    int src = edge_index[e];
    int dst = edge_index[NE + e];
    int2 at = ((const int2*)edge_attr)[e];
    int c = g_ctab[src];
    atomicAdd(&g_pk1[dst], 1ull << (9 * at.x));
    atomicAdd(&g_pk2[dst], (1ull << (6 * at.y)) + (1ull << (18 + 5 * c)));
}

__device__ __forceinline__ int node_deg(int i) {
    unsigned long long p = g_pk1[i];
    int d = 0;
#pragma unroll
    for (int t = 0; t < 7; t++) d += (int)((p >> (9 * t)) & 511ull);
    return d;
}

// ---------------- single-kernel CSR scan (ticket + flag release) ----------
__global__ void scanF_kernel() {
    __shared__ int sh[SCAN_B];
    __shared__ bool lastBlk;
    int t = threadIdx.x;
    int i = blockIdx.x * SCAN_B + t;
    int d = (i < NN) ? node_deg(i) : 0;
    sh[t] = d;
    __syncthreads();
    for (int off = SCAN_B / 2; off > 0; off >>= 1) {
        if (t < off) sh[t] += sh[t + off];
        __syncthreads();
    }
    if (t == 0) {
        g_bsum[blockIdx.x] = sh[0];
        __threadfence();
        unsigned tk = atomicAdd(&g_tick, 1u);
        lastBlk = (tk == gridDim.x - 1);
    }
    __syncthreads();
    if (lastBlk) {
        __threadfence();
        int v = (t < SCAN_G) ? g_bsum[t] : 0;
        sh[t] = v;
        __syncthreads();
        for (int off = 1; off < SCAN_B; off <<= 1) {
            int u = (t >= off) ? sh[t - off] : 0;
            __syncthreads();
            sh[t] += u;
            __syncthreads();
        }
        if (t < SCAN_G) g_boff[t] = (t == 0) ? 0 : sh[t - 1];
        __threadfence();
        __syncthreads();
        if (t == 0) atomicExch(&g_flag, 1u);
    }
    if (t == 0) {
        while (atomicAdd(&g_flag, 0u) == 0u) {}
    }
    __syncthreads();
    __threadfence();
    sh[t] = d;
    __syncthreads();
    for (int off = 1; off < SCAN_B; off <<= 1) {
        int v = (t >= off) ? sh[t - off] : 0;
        __syncthreads();
        sh[t] += v;
        __syncthreads();
    }
    if (i < NN) {
        int excl = g_boff[blockIdx.x] + sh[t] - d;
        g_rowptr[i] = excl;
        g_wr[i] = excl;
        if (i == NN - 1) g_rowptr[NN] = excl + d;
    }
}

__global__ void scatter_kernel(const int* __restrict__ edge_index) {
    int e = blockIdx.x * blockDim.x + threadIdx.x;
    if (e >= NE) return;
    int src = edge_index[e];
    int dst = edge_index[NE + e];
    int pos = atomicAdd(&g_wr[dst], 1);
    g_col[pos] = src;
}

// ---------------- layer-0 aggregation: pure count-based ----------
__global__ __launch_bounds__(256) void aggregate0_kernel(
        const float* __restrict__ e1l, const float* __restrict__ e2l) {
    __shared__ float4 ht[9 * 32];
    __shared__ float4 se[(7 + 3) * 32];
    int tid = threadIdx.x;
    for (int i = tid; i < 9 * 32; i += 256) ht[i] = ((const float4*)g_htab)[i];
    for (int i = tid; i < 320; i += 256)
        se[i] = (i < 224) ? ((const float4*)e1l)[i] : ((const float4*)e2l)[i - 224];
    __syncthreads();

    int warp = tid >> 5;
    int lane = tid & 31;
    int v = blockIdx.x * 8 + warp;
    if (v >= NN) return;

    unsigned long long p1 = g_pk1[v];
    unsigned long long p2 = g_pk2[v];

    float4 acc = ht[g_ctab[v] * 32 + lane];
    float4 t4 = se[4 * 32 + lane];
    acc.x += t4.x; acc.y += t4.y; acc.z += t4.z; acc.w += t4.w;
    t4 = se[7 * 32 + lane];
    acc.x += t4.x; acc.y += t4.y; acc.z += t4.z; acc.w += t4.w;

#pragma unroll
    for (int t = 0; t < 7; t++) {
        int c = (int)((p1 >> (9 * t)) & 511ull);
        if (c) {
            float fc = (float)c;
            float4 ev = se[t * 32 + lane];
            acc.x += fc * ev.x; acc.y += fc * ev.y; acc.z += fc * ev.z; acc.w += fc * ev.w;
        }
    }
#pragma unroll
    for (int t = 0; t < 3; t++) {
        int c = (int)((p2 >> (6 * t)) & 63ull);
        if (c) {
            float fc = (float)c;
            float4 ev = se[(7 + t) * 32 + lane];
            acc.x += fc * ev.x; acc.y += fc * ev.y; acc.z += fc * ev.z; acc.w += fc * ev.w;
        }
    }
#pragma unroll
    for (int c = 0; c < 9; c++) {
        int k = (int)((p2 >> (18 + 5 * c)) & 31ull);
        if (k) {
            float fk = (float)k;
            float4 ev = ht[c * 32 + lane];
            acc.x += fk * ev.x; acc.y += fk * ev.y; acc.z += fk * ev.z; acc.w += fk * ev.w;
        }
    }
    uint16_t h0, h1, h2, h3, l0, l1, l2, l3;
    split_f16(acc.x, h0, l0);
    split_f16(acc.y, h1, l1);
    split_f16(acc.z, h2, l2);
    split_f16(acc.w, h3, l3);
    uint2 hv2, lv2;
    hv2.x = (uint32_t)h0 | ((uint32_t)h1 << 16);
    hv2.y = (uint32_t)h2 | ((uint32_t)h3 << 16);
    lv2.x = (uint32_t)l0 | ((uint32_t)l1 << 16);
    lv2.y = (uint32_t)l2 | ((uint32_t)l3 << 16);
    *(uint2*)(g_a1 + (size_t)v * 256 + lane * 4) = hv2;
    *(uint2*)(g_a1 + (size_t)v * 256 + 128 + lane * 4) = lv2;
}

// ---------------- layer-1 aggregation: fp16 gathers + fused BN+relu --------
__global__ __launch_bounds__(256) void aggregate1_kernel(
        const uint16_t* __restrict__ Hh,
        const float* __restrict__ e1l, const float* __restrict__ e2l,
        const float* __restrict__ gamma, const float* __restrict__ beta,
        const float* __restrict__ ssum, const float* __restrict__ ssq) {
    __shared__ float4 se[(7 + 3) * 32];
    for (int i = threadIdx.x; i < 320; i += 256)
        se[i] = (i < 224) ? ((const float4*)e1l)[i] : ((const float4*)e2l)[i - 224];
    __syncthreads();

    int tid = threadIdx.x;
    int warp = tid >> 5;
    int lane = tid & 31;
    int v = blockIdx.x * 8 + warp;
    if (v >= NN) return;

    int cc = lane * 4;
    float invn = 1.0f / (float)NN;
    float scl[4], sft[4];
#pragma unroll
    for (int k = 0; k < 4; k++) {
        float mu = ssum[cc + k] * invn;
        float var = ssq[cc + k] * invn - mu * mu;
        float rs = rsqrtf(var + BN_EPS);
        scl[k] = gamma[cc + k] * rs;
        sft[k] = beta[cc + k] - mu * scl[k];
    }

    auto cvt = [&](uint2 raw) -> float4 {
        float2 f0 = __half22float2(*reinterpret_cast<const __half2*>(&raw.x));
        float2 f1 = __half22float2(*reinterpret_cast<const __half2*>(&raw.y));
        float4 x;
        x.x = fmaxf(fmaf(f0.x, scl[0], sft[0]), 0.f);
        x.y = fmaxf(fmaf(f0.y, scl[1], sft[1]), 0.f);
        x.z = fmaxf(fmaf(f1.x, scl[2], sft[2]), 0.f);
        x.w = fmaxf(fmaf(f1.y, scl[3], sft[3]), 0.f);
        return x;
    };

    float4 acc = cvt(*(const uint2*)(Hh + (size_t)v * DD + lane * 4));
    float4 t4 = se[4 * 32 + lane];
    acc.x += t4.x; acc.y += t4.y; acc.z += t4.z; acc.w += t4.w;
    t4 = se[7 * 32 + lane];
    acc.x += t4.x; acc.y += t4.y; acc.z += t4.z; acc.w += t4.w;

    float4 acc2 = make_float4(0.f, 0.f, 0.f, 0.f);
    int beg = g_rowptr[v];
    int end = g_rowptr[v + 1];
    int j = beg;
    for (; j + 7 < end; j += 8) {
        uint2 raw[8];
#pragma unroll
        for (int q = 0; q < 8; q++)
            raw[q] = *(const uint2*)(Hh + (size_t)g_col[j + q] * DD + lane * 4);
#pragma unroll
        for (int q = 0; q < 8; q += 2) {
            float4 a0 = cvt(raw[q]);
            float4 a1 = cvt(raw[q + 1]);
            if (q & 2) {
                acc2.x += a0.x + a1.x; acc2.y += a0.y + a1.y;
                acc2.z += a0.z + a1.z; acc2.w += a0.w + a1.w;
            } else {
                acc.x += a0.x + a1.x; acc.y += a0.y + a1.y;
                acc.z += a0.z + a1.z; acc.w += a0.w + a1.w;
            }
        }
    }
    for (; j < end; j++) {
        float4 hv = cvt(*(const uint2*)(Hh + (size_t)g_col[j] * DD + lane * 4));
        acc.x += hv.x; acc.y += hv.y; acc.z += hv.z; acc.w += hv.w;
    }
    acc.x += acc2.x; acc.y += acc2.y; acc.z += acc2.z; acc.w += acc2.w;

    unsigned long long p1 = g_pk1[v];
    unsigned long long p2 = g_pk2[v];
#pragma unroll
    for (int t = 0; t < 7; t++) {
        int c = (int)((p1 >> (9 * t)) & 511ull);
        if (c) {
            float fc = (float)c;
            float4 ev = se[t * 32 + lane];
            acc.x += fc * ev.x; acc.y += fc * ev.y; acc.z += fc * ev.z; acc.w += fc * ev.w;
        }
    }
#pragma unroll
    for (int t = 0; t < 3; t++) {
        int c = (int)((p2 >> (6 * t)) & 63ull);
        if (c) {
            float fc = (float)c;
            float4 ev = se[(7 + t) * 32 + lane];
            acc.x += fc * ev.x; acc.y += fc * ev.y; acc.z += fc * ev.z; acc.w += fc * ev.w;
        }
    }
    uint16_t h0, h1, h2, h3, l0, l1, l2, l3;
    split_f16(acc.x, h0, l0);
    split_f16(acc.y, h1, l1);
    split_f16(acc.z, h2, l2);
    split_f16(acc.w, h3, l3);
    uint2 hv2, lv2;
    hv2.x = (uint32_t)h0 | ((uint32_t)h1 << 16);
    hv2.y = (uint32_t)h2 | ((uint32_t)h3 << 16);
    lv2.x = (uint32_t)l0 | ((uint32_t)l1 << 16);
    lv2.y = (uint32_t)l2 | ((uint32_t)l3 << 16);
    *(uint2*)(g_a1 + (size_t)v * 256 + lane * 4) = hv2;
    *(uint2*)(g_a1 + (size_t)v * 256 + 128 + lane * 4) = lv2;
}

// ---------------- fused MLP (256 threads, 8 warps as 2x4) -----------------
// mid = relu(A x W1 + b1); out = mid x W2 + b2.
// A [MP,256] fp16 (hi|lo). B1 [256n,256k] (hi|hi dup). B2 [128n,512k] (256 used).
// mid: 8 SW128 tiles of [128,64] fp16 in smem (hi 0..3, lo 4..7).
template <bool OUT16>
__global__ void __launch_bounds__(256, 1)
mlp_fused_kernel(const uint16_t* __restrict__ A,
                 const uint16_t* __restrict__ B1m,
                 const uint16_t* __restrict__ B2m,
                 const float* __restrict__ bias1,
                 const float* __restrict__ bias2,
                 float* __restrict__ outF,
                 uint16_t* __restrict__ outF16,
                 float* __restrict__ statSum,
                 float* __restrict__ statSq) {
    extern __shared__ char smem[];
    float* sB1 = (float*)smem;                   // 256 f
    float* sB2 = (float*)(smem + 1024);          // 128 f
    char* scrA = smem + 2048;                    // 2 x 16KB (ph1 A / ph2 B2)
    char* scrB = smem + 2048 + 32768;            // 32KB (ph1 B1, single buf)
    char* mid  = smem + 67584;                   // 8 x 16KB
    const int tid = threadIdx.x;
    const int wid = tid >> 5;
    const int lane = tid & 31;
    const int m0 = blockIdx.x * 128;
    const int wm = (wid >> 2) * 64;
    const int wn2 = (wid & 3) * 64;              // phase 1 (N=256)
    const int wn3 = (wid & 3) * 32;              // phase 2 (N=128)

    sB1[tid] = bias1[tid];
    if (tid < 128) sB2[tid] = bias2[tid];

    // ================= phase 1 =================
    float acc1[4][8][4];
#pragma unroll
    for (int i = 0; i < 4; i++)
#pragma unroll
        for (int j = 0; j < 8; j++)
#pragma unroll
            for (int k = 0; k < 4; k++) acc1[i][j][k] = 0.f;

    auto loadA1 = [&](int c, int buf) {
        const uint16_t* Ag = A + (size_t)m0 * 256 + c * 64;
        uint32_t ab = s2u(scrA + buf * 16384);
#pragma unroll
        for (int i = 0; i < 4; i++) {
            int idx = tid + i * 256;
            int r = idx >> 3, u = idx & 7;
            CP_A16(ab + SWZ(r * 128 + u * 16), Ag + (size_t)r * 256 + u * 8);
        }
    };
    auto loadB1c = [&](int c) {
        const uint16_t* Bg = B1m + c * 64;
        uint32_t bb = s2u(scrB);
#pragma unroll
        for (int i = 0; i < 8; i++) {
            int idx = tid + i * 256;
            int r = idx >> 3, u = idx & 7;
            CP_A16(bb + SWZ(r * 128 + u * 16), Bg + (size_t)r * 256 + u * 8);
        }
    };

    loadA1(0, 0); CP_COMMIT();
    for (int c = 0; c < 4; c++) {
        int buf = c & 1;
        loadB1c(c); CP_COMMIT();
        if (c < 3) { loadA1(c + 1, buf ^ 1); CP_COMMIT(); CP_WAIT(1); }
        else CP_WAIT(0);
        __syncthreads();
        uint32_t aBase = s2u(scrA + buf * 16384);
        uint32_t bBase = s2u(scrB);
#pragma unroll
        for (int ks = 0; ks < 4; ks++) {
            int k0b = ks * 32;
            uint32_t af[4][4];
#pragma unroll
            for (int mt = 0; mt < 4; mt++) {
                int row = wm + mt * 16 + (lane & 15);
                LDSM_X4(af[mt][0], af[mt][1], af[mt][2], af[mt][3],
                        aBase + SWZ(row * 128 + k0b + ((lane >> 4) << 4)));
            }
            uint32_t bfr[8][2];
#pragma unroll
            for (int p = 0; p < 4; p++) {
                int g = lane >> 3;
                int nrow = wn2 + p * 16 + (lane & 7) + ((g >> 1) << 3);
                uint32_t r0, r1, r2, r3;
                LDSM_X4(r0, r1, r2, r3, bBase + SWZ(nrow * 128 + k0b + ((g & 1) << 4)));
                bfr[2 * p][0] = r0; bfr[2 * p][1] = r1;
                bfr[2 * p + 1][0] = r2; bfr[2 * p + 1][1] = r3;
            }
#pragma unroll
            for (int mt = 0; mt < 4; mt++)
#pragma unroll
                for (int nt = 0; nt < 8; nt++)
                    MMA16816(acc1[mt][nt], af[mt], bfr[nt]);
        }
        __syncthreads();
    }

    // phase-1 epilogue: bias + relu + fp16 split -> mid tiles
#pragma unroll
    for (int nt = 0; nt < 8; nt++) {
        int cl = wn2 + nt * 8 + 2 * (lane & 3);   // 0..255
        float b0 = sB1[cl], b1v = sB1[cl + 1];
        int th = cl >> 6;                          // hi tile 0..3
        int ln2 = (cl & 63) * 2;                   // byte offset in 128B row
#pragma unroll
        for (int mt = 0; mt < 4; mt++) {
#pragma unroll
            for (int h = 0; h < 2; h++) {
                int m = wm + mt * 16 + (lane >> 2) + h * 8;   // local row
                float v0 = fmaxf(acc1[mt][nt][2 * h] + b0, 0.f);
                float v1 = fmaxf(acc1[mt][nt][2 * h + 1] + b1v, 0.f);
                uint16_t h0, l0, h1, l1;
                split_f16(v0, h0, l0);
                split_f16(v1, h1, l1);
                *(uint32_t*)(mid + th * 16384 + SWZ(m * 128 + ln2)) =
                    (uint32_t)h0 | ((uint32_t)h1 << 16);
                *(uint32_t*)(mid + (4 + th) * 16384 + SWZ(m * 128 + ln2)) =
                    (uint32_t)l0 | ((uint32_t)l1 << 16);
            }
        }
    }
    __syncthreads();

    // ================= phase 2 =================
    float acc2[4][4][4];
#pragma unroll
    for (int i = 0; i < 4; i++)
#pragma unroll
        for (int j = 0; j < 4; j++)
#pragma unroll
            for (int k = 0; k < 4; k++) acc2[i][j][k] = 0.f;

    auto loadB2c = [&](int c, int buf) {
        const uint16_t* Bg = B2m + c * 64;
        uint32_t bb = s2u(scrA + buf * 16384);
#pragma unroll
        for (int i = 0; i < 4; i++) {
            int idx = tid + i * 256;
            int r = idx >> 3, u = idx & 7;
            CP_A16(bb + SWZ(r * 128 + u * 16), Bg + (size_t)r * 512 + u * 8);
        }
    };

    loadB2c(0, 0); CP_COMMIT();
    for (int c = 0; c < 4; c++) {
        int buf = c & 1;
        if (c < 3) { loadB2c(c + 1, buf ^ 1); CP_COMMIT(); CP_WAIT(1); }
        else CP_WAIT(0);
        __syncthreads();
        uint32_t bBase = s2u(scrA + buf * 16384);
#pragma unroll
        for (int part = 0; part < 2; part++) {
            uint32_t aBase = s2u(mid + (part * 4 + c) * 16384);
#pragma unroll
            for (int ks = 0; ks < 4; ks++) {
                int k0b = ks * 32;
                uint32_t af[4][4];
#pragma unroll
                for (int mt = 0; mt < 4; mt++) {
                    int row = wm + mt * 16 + (lane & 15);
                    LDSM_X4(af[mt][0], af[mt][1], af[mt][2], af[mt][3],
                            aBase + SWZ(row * 128 + k0b + ((lane >> 4) << 4)));
                }
                uint32_t bfr[4][2];
#pragma unroll
                for (int p = 0; p < 2; p++) {
                    int g = lane >> 3;
                    int nrow = wn3 + p * 16 + (lane & 7) + ((g >> 1) << 3);
                    uint32_t r0, r1, r2, r3;
                    LDSM_X4(r0, r1, r2, r3,
                            bBase + SWZ(nrow * 128 + k0b + ((g & 1) << 4)));
                    bfr[2 * p][0] = r0; bfr[2 * p][1] = r1;
                    bfr[2 * p + 1][0] = r2; bfr[2 * p + 1][1] = r3;
                }
#pragma unroll
                for (int mt = 0; mt < 4; mt++)
#pragma unroll
                    for (int nt = 0; nt < 4; nt++)
                        MMA16816(acc2[mt][nt], af[mt], bfr[nt]);
            }
        }
        __syncthreads();
    }

    // phase-2 epilogue: bias + store + fused BN stats
#pragma unroll
    for (int nt = 0; nt < 4; nt++) {
        int cl = wn3 + nt * 8 + 2 * (lane & 3);
        float b0 = sB2[cl], b1v = sB2[cl + 1];
        float s0 = 0.f, s1 = 0.f, q0 = 0.f, q1 = 0.f;
#pragma unroll
        for (int mt = 0; mt < 4; mt++) {
#pragma unroll
            for (int h = 0; h < 2; h++) {
                int m = m0 + wm + mt * 16 + (lane >> 2) + h * 8;
                float v0 = acc2[mt][nt][2 * h] + b0;
                float v1 = acc2[mt][nt][2 * h + 1] + b1v;
                if (m < NN) {
                    if (OUT16) {
                        __half2 hp = __floats2half2_rn(v0, v1);
                        *(uint32_t*)(outF16 + (size_t)m * 128 + cl) =
                            *reinterpret_cast<uint32_t*>(&hp);
                    } else {
                        float2 v; v.x = v0; v.y = v1;
                        *(float2*)(outF + (size_t)m * 128 + cl) = v;
                    }
                    s0 += v0; s1 += v1;
                    q0 += v0 * v0; q1 += v1 * v1;
                }
            }
        }
#pragma unroll
        for (int off = 16; off >= 4; off >>= 1) {
            s0 += __shfl_down_sync(0xffffffff, s0, off);
            s1 += __shfl_down_sync(0xffffffff, s1, off);
            q0 += __shfl_down_sync(0xffffffff, q0, off);
            q1 += __shfl_down_sync(0xffffffff, q1, off);
        }
        if (lane < 4) {
            atomicAdd(&statSum[cl], s0);
            atomicAdd(&statSum[cl + 1], s1);
            atomicAdd(&statSq[cl], q0);
            atomicAdd(&statSq[cl + 1], q1);
        }
    }
}

// ---------------- final BN apply ----------------
__global__ void bn_apply_kernel(const float* __restrict__ X,
                                const float* __restrict__ gamma,
                                const float* __restrict__ beta,
                                const float* __restrict__ ssum,
                                const float* __restrict__ ssq,
                                float* __restrict__ Y) {
    int idx = blockIdx.x * blockDim.x + threadIdx.x;
    if (idx >= NN * (DD / 4)) return;
    int v = idx >> 5;
    int c4 = idx & 31;
    int c = c4 * 4;
    float4 x = ((const float4*)(X + (size_t)v * DD))[c4];
    float invn = 1.0f / (float)NN;
    float o[4];
    float xi[4] = {x.x, x.y, x.z, x.w};
#pragma unroll
    for (int k = 0; k < 4; k++) {
        float mu = ssum[c + k] * invn;
        float var = ssq[c + k] * invn - mu * mu;
        float rs = rsqrtf(var + BN_EPS);
        o[k] = gamma[c + k] * (xi[k] - mu) * rs + beta[c + k];
    }
    ((float4*)(Y + (size_t)v * DD))[c4] = make_float4(o[0], o[1], o[2], o[3]);
}

// ---------------- launch ----------------
extern "C" void kernel_launch(void* const* d_in, const int* in_sizes, int n_in,
                              void* d_out, int out_size) {
    const int* x          = (const int*)d_in[0];
    const int* edge_index = (const int*)d_in[1];
    const int* edge_attr  = (const int*)d_in[2];
    const float* xemb1 = (const float*)d_in[4];
    const float* xemb2 = (const float*)d_in[5];
    const float* e1    = (const float*)d_in[6];
    const float* e2    = (const float*)d_in[7];
    const float* W1    = (const float*)d_in[8];
    const float* b1    = (const float*)d_in[9];
    const float* W2    = (const float*)d_in[10];
    const float* b2    = (const float*)d_in[11];
    const float* gamma = (const float*)d_in[12];
    const float* beta  = (const float*)d_in[13];
    float* out = (float*)d_out;

    float *p_h2, *p_sum, *p_sq;
    uint16_t *p_h2h, *p_a1, *p_b1, *p_b2;
    cudaGetSymbolAddress((void**)&p_h2,  g_h2);
    cudaGetSymbolAddress((void**)&p_h2h, g_h2h);
    cudaGetSymbolAddress((void**)&p_a1,  g_a1);
    cudaGetSymbolAddress((void**)&p_b1,  g_b1);
    cudaGetSymbolAddress((void**)&p_b2,  g_b2);
    cudaGetSymbolAddress((void**)&p_sum, g_colsum);
    cudaGetSymbolAddress((void**)&p_sq,  g_colsq);

    constexpr int SMEM_F = 67584 + 8 * 16384;   // 198656 B
    cudaFuncSetAttribute(mlp_fused_kernel<true>,
                         cudaFuncAttributeMaxDynamicSharedMemorySize, SMEM_F);
    cudaFuncSetAttribute(mlp_fused_kernel<false>,
                         cudaFuncAttributeMaxDynamicSharedMemorySize, SMEM_F);

    static cudaStream_t sCSR = nullptr, sWB = nullptr;
    static cudaEvent_t evInit = nullptr, evHist = nullptr, evWB = nullptr, evCSR = nullptr;
    if (!sCSR) {
        cudaStreamCreateWithFlags(&sCSR, cudaStreamNonBlocking);
        cudaStreamCreateWithFlags(&sWB, cudaStreamNonBlocking);
        cudaEventCreateWithFlags(&evInit, cudaEventDisableTiming);
        cudaEventCreateWithFlags(&evHist, cudaEventDisableTiming);
        cudaEventCreateWithFlags(&evWB, cudaEventDisableTiming);
        cudaEventCreateWithFlags(&evCSR, cudaEventDisableTiming);
    }

    // weight builds overlap everything up to first GEMM
    cudaEventRecord(evInit, 0);
    cudaStreamWaitEvent(sWB, evInit, 0);
    setupB_kernel<<<(UB1 + 255) / 256, 256, 0, sWB>>>(W1, W2);
    cudaEventRecord(evWB, sWB);

    setupA_kernel<<<(UA4 + 255) / 256, 256>>>(x, xemb1, xemb2);
    hist_kernel<<<(NE + 255) / 256, 256>>>(edge_index, edge_attr);
    cudaEventRecord(evHist, 0);

    // CSR chain on side stream (needed only by layer-1 aggregation)
    cudaStreamWaitEvent(sCSR, evHist, 0);
    scanF_kernel<<<SCAN_G, SCAN_B, 0, sCSR>>>();
    scatter_kernel<<<(NE + 255) / 256, 256, 0, sCSR>>>(edge_index);
    cudaEventRecord(evCSR, sCSR);

    // layer 0
    aggregate0_kernel<<<(NN + 7) / 8, 256>>>(e1, e2);
    cudaStreamWaitEvent(0, evWB, 0);
    mlp_fused_kernel<true><<<MP / 128, 256, SMEM_F>>>(
        p_a1, p_b1, p_b2, b1, b2, nullptr, p_h2h, p_sum, p_sq);

    // layer 1
    cudaStreamWaitEvent(0, evCSR, 0);
    aggregate1_kernel<<<(NN + 7) / 8, 256>>>(
        p_h2h, e1 + 7 * DD, e2 + 3 * DD, gamma, beta, p_sum, p_sq);
    mlp_fused_kernel<false><<<MP / 128, 256, SMEM_F>>>(
        p_a1, p_b1 + 65536, p_b2 + 65536, b1 + 2 * DD, b2 + DD,
        p_h2, nullptr, p_sum + DD, p_sq + DD);

    bn_apply_kernel<<<(NN * 32 + 255) / 256, 256>>>(
        p_h2, gamma + DD, beta + DD, p_sum + DD, p_sq + DD, out);
}